// round 2
// baseline (speedup 1.0000x reference)
#include <cuda_runtime.h>
#include <cuda_bf16.h>
#include <math_constants.h>

// Problem constants
#define N_ROWS   65536   // 16*4096
#define EMB_DIM  64
#define N_CODES  8192
#define NZ_ELEMS 4194304 // N_ROWS * EMB_DIM
#define M_TILE   64      // rows per block
#define C_TILE   64      // codes per tile
#define N_BLOCKS (N_ROWS / M_TILE)  // 1024
#define BETA     0.25f

// Scratch (no cudaMalloc allowed)
__device__ float g_enorm[N_CODES];
__device__ int   g_idx_buf[N_ROWS];
__device__ float g_partials[N_BLOCKS];

// ---------------------------------------------------------------------------
// Kernel 1: per-code squared norms  b_j = sum_k fl(e^2), sequential adds.
// Emulates jnp.sum(embedding**2, axis=1): square rounds, then sequential
// fp32 adds (NO fma contraction -> use __fmul_rn/__fadd_rn intrinsics).
// ---------------------------------------------------------------------------
__global__ void vq_enorm_kernel(const float* __restrict__ emb) {
    int c = blockIdx.x * blockDim.x + threadIdx.x;
    if (c < N_CODES) {
        const float* row = emb + (size_t)c * EMB_DIM;
        float s = 0.f;
#pragma unroll
        for (int k = 0; k < EMB_DIM; ++k) {
            float v = row[k];
            s = __fadd_rn(s, __fmul_rn(v, v));
        }
        g_enorm[c] = s;
    }
}

// ---------------------------------------------------------------------------
// Kernel 2: fused distance-GEMM + argmin + z_q write + per-block loss partial
//   d_j = fl( fl(a_r + b_j) - 2*c_rj )   with
//   a_r = sequential sum of fl(z^2), c_rj = sequential fma dot (k=0..63).
//   This reproduces the reference fp32 rounding so quantization ties break
//   identically (argmin first-index).
// ---------------------------------------------------------------------------
__global__ void __launch_bounds__(256, 2)
vq_main_kernel(const float* __restrict__ z,
               const float* __restrict__ emb,
               float* __restrict__ zq_out) {
    __shared__ __align__(16) float z_s[EMB_DIM][M_TILE + 4]; // [k][row]
    __shared__ __align__(16) float e_s[EMB_DIM][C_TILE + 4]; // [k][code]
    __shared__ float en_s[C_TILE];   // b_j for current tile
    __shared__ float a_s[M_TILE];    // a_r per row
    __shared__ int   idx_s[M_TILE];
    __shared__ float red_s[256];

    const int tid = threadIdx.x;
    const int tx  = tid & 15;       // code group
    const int ty  = tid >> 4;       // row group
    const long row0 = (long)blockIdx.x * M_TILE;

    // Load z tile transposed: z_s[k][r]
    for (int i = tid; i < M_TILE * EMB_DIM; i += 256) {
        int r = i >> 6, k = i & 63;
        z_s[k][r] = z[(row0 + r) * EMB_DIM + k];
    }
    __syncthreads();

    // a_r = sum_k fl(z^2), sequential fp32 adds (matches jnp.sum(z**2, -1))
    if (tid < M_TILE) {
        float s = 0.f;
#pragma unroll
        for (int k = 0; k < EMB_DIM; ++k) {
            float v = z_s[k][tid];
            s = __fadd_rn(s, __fmul_rn(v, v));
        }
        a_s[tid] = s;
    }
    // a_s visibility to all threads is covered by the first sync in the loop.

    float best[4];
    int   bidx[4];
    float arow[4];
#pragma unroll
    for (int r = 0; r < 4; ++r) { best[r] = CUDART_INF_F; bidx[r] = 0; }

    for (int t = 0; t < N_CODES / C_TILE; ++t) {
        const int c0 = t * C_TILE;
        __syncthreads();  // previous tile consumed; a_s/z_s ready at t=0
        // Load code tile transposed: e_s[k][c]
        for (int i = tid; i < C_TILE * EMB_DIM; i += 256) {
            int c = i >> 6, k = i & 63;
            e_s[k][c] = emb[(size_t)(c0 + c) * EMB_DIM + k];
        }
        if (tid < C_TILE) en_s[tid] = g_enorm[c0 + tid];
        __syncthreads();

        if (t == 0) {
#pragma unroll
            for (int r = 0; r < 4; ++r) arow[r] = a_s[ty * 4 + r];
        }

        float dot[4][4];
#pragma unroll
        for (int r = 0; r < 4; ++r)
#pragma unroll
            for (int c = 0; c < 4; ++c) dot[r][c] = 0.f;

        // Sequential k=0..63, single fma accumulator per (r,c):
        // matches Eigen gebp / XLA-CPU fp32 gemm accumulation.
#pragma unroll 8
        for (int k = 0; k < EMB_DIM; ++k) {
            float4 zz = *reinterpret_cast<const float4*>(&z_s[k][ty * 4]);
            float4 ee = *reinterpret_cast<const float4*>(&e_s[k][tx * 4]);
            float zr[4] = { zz.x, zz.y, zz.z, zz.w };
            float ec[4] = { ee.x, ee.y, ee.z, ee.w };
#pragma unroll
            for (int r = 0; r < 4; ++r)
#pragma unroll
                for (int c = 0; c < 4; ++c)
                    dot[r][c] = fmaf(zr[r], ec[c], dot[r][c]);
        }

        // d = fl( fl(a+b) - 2c ): fmaf(-2, c, t) rounds once, 2c exact —
        // bit-identical to reference's (a+b) - 2*c.
#pragma unroll
        for (int c = 0; c < 4; ++c) {
            const int code = c0 + tx * 4 + c;
            const float b = en_s[tx * 4 + c];
#pragma unroll
            for (int r = 0; r < 4; ++r) {
                float tsum = __fadd_rn(arow[r], b);
                float d = fmaf(-2.f, dot[r][c], tsum);
                if (d < best[r]) { best[r] = d; bidx[r] = code; }
            }
        }
    }

    // Argmin reduction across the 16 tx lanes (half-warp), first-index tiebreak
#pragma unroll
    for (int off = 1; off < 16; off <<= 1) {
#pragma unroll
        for (int r = 0; r < 4; ++r) {
            float ov = __shfl_xor_sync(0xffffffffu, best[r], off);
            int   oi = __shfl_xor_sync(0xffffffffu, bidx[r], off);
            if (ov < best[r] || (ov == best[r] && oi < bidx[r])) {
                best[r] = ov; bidx[r] = oi;
            }
        }
    }
    if (tx == 0) {
#pragma unroll
        for (int r = 0; r < 4; ++r) idx_s[ty * 4 + r] = bidx[r];
    }
    __syncthreads();

    if (tid < M_TILE) g_idx_buf[row0 + tid] = idx_s[tid];

    // z_q write + loss partial
    float lsum = 0.f;
    for (int i = tid; i < M_TILE * EMB_DIM; i += 256) {
        int r = i >> 6, k = i & 63;
        float e = emb[(size_t)idx_s[r] * EMB_DIM + k];
        float diff = e - z_s[k][r];
        lsum = fmaf(diff, diff, lsum);
        zq_out[(row0 + r) * EMB_DIM + k] = e;
    }

    // Deterministic block tree reduction
    red_s[tid] = lsum;
    __syncthreads();
#pragma unroll
    for (int s = 128; s > 0; s >>= 1) {
        if (tid < s) red_s[tid] += red_s[tid + s];
        __syncthreads();
    }
    if (tid == 0) g_partials[blockIdx.x] = red_s[0];
}

// ---------------------------------------------------------------------------
// Kernel 3: deterministic final loss reduction
// ---------------------------------------------------------------------------
__global__ void vq_loss_kernel(float* __restrict__ out, int loss_off) {
    __shared__ float red_s[256];
    const int tid = threadIdx.x;
    float s = 0.f;
#pragma unroll
    for (int j = 0; j < N_BLOCKS / 256; ++j)   // fixed order: deterministic
        s += g_partials[tid + j * 256];
    red_s[tid] = s;
    __syncthreads();
#pragma unroll
    for (int st = 128; st > 0; st >>= 1) {
        if (tid < st) red_s[tid] += red_s[tid + st];
        __syncthreads();
    }
    if (tid == 0 && loss_off >= 0)
        out[loss_off] = (1.0f + BETA) * (red_s[0] / (float)NZ_ELEMS);
}

// ---------------------------------------------------------------------------
// Kernel 4: indices -> float into output tail
// ---------------------------------------------------------------------------
__global__ void vq_idx_kernel(float* __restrict__ out_idx) {
    int i = blockIdx.x * blockDim.x + threadIdx.x;
    if (i < N_ROWS) out_idx[i] = (float)g_idx_buf[i];
}

// ---------------------------------------------------------------------------
extern "C" void kernel_launch(void* const* d_in, const int* in_sizes, int n_in,
                              void* d_out, int out_size) {
    const float* z   = (const float*)d_in[0];
    const float* emb = (const float*)d_in[1];
    float* out = (float*)d_out;

    vq_enorm_kernel<<<(N_CODES + 255) / 256, 256>>>(emb);
    vq_main_kernel<<<N_BLOCKS, 256>>>(z, emb, out);

    // Infer output layout from out_size: assume return order (z_q, loss, idx)
    long loss_off = -1, idx_off = -1;
    if (out_size >= NZ_ELEMS + 1 + N_ROWS) {        // z_q, loss, idx
        loss_off = NZ_ELEMS; idx_off = NZ_ELEMS + 1;
    } else if (out_size == NZ_ELEMS + N_ROWS) {     // z_q, idx
        idx_off = NZ_ELEMS;
    } else if (out_size == NZ_ELEMS + 1) {          // z_q, loss
        loss_off = NZ_ELEMS;
    }

    vq_loss_kernel<<<1, 256>>>(out, (int)loss_off);
    if (idx_off >= 0)
        vq_idx_kernel<<<(N_ROWS + 255) / 256, 256>>>(out + idx_off);
}

// round 3
// speedup vs baseline: 1.5130x; 1.5130x over previous
#include <cuda_runtime.h>
#include <math_constants.h>

// Problem constants
#define N_ROWS   65536   // 16*4096
#define EMB_DIM  64
#define N_CODES  8192
#define NZ_ELEMS 4194304 // N_ROWS * EMB_DIM
#define M_TILE   64      // rows per block
#define CT       256     // codes per tile
#define NT       (N_CODES / CT)     // 32
#define N_BLOCKS (N_ROWS / M_TILE)  // 1024
#define BETA     0.25f

// Scratch (no cudaMalloc allowed)
__device__ float g_enorm[N_CODES];
__device__ float g_embT[EMB_DIM * N_CODES];   // [k][c] transposed codebook (2MB)
__device__ int   g_idx_buf[N_ROWS];
__device__ float g_partials[N_BLOCKS];

// Dynamic SMEM layout (bytes)
#define SM_E      0                       // 2 x [64][256] f32 = 131072
#define SM_E_BUF  65536
#define SM_ZD     131072                  // [64][66] float2 (dup z) = 33792
#define ZD_STRIDE 66
#define SM_A      (SM_ZD + 33792)         // 64 f32
#define SM_IDX    (SM_A + 256)            // 64 i32
#define SM_RED    (SM_IDX + 256)          // 256 f32
#define SM_TOTAL  (SM_RED + 1024)         // 166400

// ---------------------------------------------------------------------------
__device__ __forceinline__ void fma2(unsigned long long& d,
                                     unsigned long long a,
                                     unsigned long long b) {
    asm("fma.rn.f32x2 %0, %1, %2, %0;" : "+l"(d) : "l"(a), "l"(b));
}
__device__ __forceinline__ void unpack2(unsigned long long v, float& lo, float& hi) {
    unsigned int ulo, uhi;
    asm("mov.b64 {%0, %1}, %2;" : "=r"(ulo), "=r"(uhi) : "l"(v));
    lo = __int_as_float(ulo); hi = __int_as_float(uhi);
}
__device__ __forceinline__ void cp_async16(unsigned int smem_addr, const void* gsrc) {
    asm volatile("cp.async.cg.shared.global [%0], [%1], 16;"
                 :: "r"(smem_addr), "l"(gsrc));
}
__device__ __forceinline__ void cp_commit() {
    asm volatile("cp.async.commit_group;");
}
__device__ __forceinline__ void cp_wait1() {
    asm volatile("cp.async.wait_group 1;");
}

// ---------------------------------------------------------------------------
// Kernel 0: transpose codebook  g_embT[k][c] = emb[c][k]   (one-time, ~10us)
// ---------------------------------------------------------------------------
__global__ void vq_transpose_kernel(const float* __restrict__ emb) {
    int idx = blockIdx.x * 256 + threadIdx.x;       // = k*8192 + c
    if (idx < EMB_DIM * N_CODES) {
        int k = idx >> 13;
        int c = idx & (N_CODES - 1);
        g_embT[idx] = emb[c * EMB_DIM + k];
    }
}

// ---------------------------------------------------------------------------
// Kernel 1: per-code squared norms (sequential fp32 adds — matches reference)
// ---------------------------------------------------------------------------
__global__ void vq_enorm_kernel(const float* __restrict__ emb) {
    int c = blockIdx.x * blockDim.x + threadIdx.x;
    if (c < N_CODES) {
        const float* row = emb + (size_t)c * EMB_DIM;
        float s = 0.f;
#pragma unroll
        for (int k = 0; k < EMB_DIM; ++k) {
            float v = row[k];
            s = __fadd_rn(s, __fmul_rn(v, v));
        }
        g_enorm[c] = s;
    }
}

// ---------------------------------------------------------------------------
// Kernel 2: fused distance + argmin + z_q + loss partial.
//   64 rows/block, 256 threads. warp w -> rows w*8..w*8+7; lane -> code pairs
//   (2*lane, 2*lane+1) + 64*m', m'=0..3 per 256-code tile.
//   Dot accumulation: packed fma.rn.f32x2, lane-wise identical to scalar fmaf
//   chain k=0..63 => bit-identical d => same argmin as round-2 (passing).
// ---------------------------------------------------------------------------
__global__ void __launch_bounds__(256, 1)
vq_main_kernel(const float* __restrict__ z,
               const float* __restrict__ emb,
               float* __restrict__ zq_out) {
    extern __shared__ char smem[];
    float2* zd    = (float2*)(smem + SM_ZD);
    float*  a_sp  = (float*)(smem + SM_A);
    int*    idx_s = (int*)(smem + SM_IDX);
    float*  red_s = (float*)(smem + SM_RED);

    const int tid  = threadIdx.x;
    const int lane = tid & 31;
    const int w    = tid >> 5;          // 0..7, rows w*8..w*8+7
    const long row0 = (long)blockIdx.x * M_TILE;

    const unsigned int smem_e0 = (unsigned int)__cvta_generic_to_shared(smem + SM_E);

    // Prologue: kick off async loads of code tiles 0 and 1
#pragma unroll
    for (int t = 0; t < 2; ++t) {
#pragma unroll
        for (int j = 0; j < 16; ++j) {
            int idx = tid + j * 256;
            int kk = idx >> 6;          // k row 0..63
            int c4 = idx & 63;          // float4 chunk within 256 codes
            cp_async16(smem_e0 + (unsigned)(t * SM_E_BUF + (kk * CT + c4 * 4) * 4),
                       g_embT + (size_t)kk * N_CODES + t * CT + c4 * 4);
        }
        cp_commit();
    }

    // Build duplicated-z tile: zd[k][r] = (v, v)
    for (int i = tid; i < M_TILE * EMB_DIM; i += 256) {
        int r = i >> 6, k = i & 63;
        float v = z[(row0 + r) * EMB_DIM + k];
        zd[k * ZD_STRIDE + r] = make_float2(v, v);
    }
    __syncthreads();

    // a_r = sequential sum of fl(z^2)  (bit-identical to reference row norm)
    if (tid < M_TILE) {
        float s = 0.f;
#pragma unroll
        for (int k = 0; k < EMB_DIM; ++k) {
            float v = zd[k * ZD_STRIDE + tid].x;
            s = __fadd_rn(s, __fmul_rn(v, v));
        }
        a_sp[tid] = s;
    }
    __syncthreads();

    float a8[8];
#pragma unroll
    for (int j = 0; j < 8; ++j) a8[j] = a_sp[w * 8 + j];

    float best[8];
    int   bidx[8];
#pragma unroll
    for (int j = 0; j < 8; ++j) { best[j] = CUDART_INF_F; bidx[j] = 0; }

    for (int t = 0; t < NT; ++t) {
        const int c0 = t * CT;
        cp_wait1();          // tile t arrived (<=1 group still in flight)
        __syncthreads();     // make all threads' cp.async data visible

        // Prefetch code norms for this thread's 8 codes (hidden by k-loop)
        float bn[8];
#pragma unroll
        for (int m = 0; m < 4; ++m) {
            bn[m * 2 + 0] = g_enorm[c0 + m * 64 + 2 * lane + 0];
            bn[m * 2 + 1] = g_enorm[c0 + m * 64 + 2 * lane + 1];
        }

        const float* es = (const float*)(smem + SM_E) + (t & 1) * (SM_E_BUF / 4);

        unsigned long long acc[8][4];
#pragma unroll
        for (int r = 0; r < 8; ++r)
#pragma unroll
            for (int m = 0; m < 4; ++m) acc[r][m] = 0ULL;

#pragma unroll 4
        for (int k = 0; k < EMB_DIM; ++k) {
            const float2* zrow = zd + k * ZD_STRIDE + w * 8;
            ulonglong2 z01 = *(const ulonglong2*)(zrow + 0);  // dup rows r0,r1
            ulonglong2 z23 = *(const ulonglong2*)(zrow + 2);
            ulonglong2 z45 = *(const ulonglong2*)(zrow + 4);
            ulonglong2 z67 = *(const ulonglong2*)(zrow + 6);
            const float* erow = es + k * CT + 2 * lane;
            unsigned long long e0 = *(const unsigned long long*)(erow + 0);
            unsigned long long e1 = *(const unsigned long long*)(erow + 64);
            unsigned long long e2 = *(const unsigned long long*)(erow + 128);
            unsigned long long e3 = *(const unsigned long long*)(erow + 192);

            fma2(acc[0][0], z01.x, e0); fma2(acc[0][1], z01.x, e1);
            fma2(acc[0][2], z01.x, e2); fma2(acc[0][3], z01.x, e3);
            fma2(acc[1][0], z01.y, e0); fma2(acc[1][1], z01.y, e1);
            fma2(acc[1][2], z01.y, e2); fma2(acc[1][3], z01.y, e3);
            fma2(acc[2][0], z23.x, e0); fma2(acc[2][1], z23.x, e1);
            fma2(acc[2][2], z23.x, e2); fma2(acc[2][3], z23.x, e3);
            fma2(acc[3][0], z23.y, e0); fma2(acc[3][1], z23.y, e1);
            fma2(acc[3][2], z23.y, e2); fma2(acc[3][3], z23.y, e3);
            fma2(acc[4][0], z45.x, e0); fma2(acc[4][1], z45.x, e1);
            fma2(acc[4][2], z45.x, e2); fma2(acc[4][3], z45.x, e3);
            fma2(acc[5][0], z45.y, e0); fma2(acc[5][1], z45.y, e1);
            fma2(acc[5][2], z45.y, e2); fma2(acc[5][3], z45.y, e3);
            fma2(acc[6][0], z67.x, e0); fma2(acc[6][1], z67.x, e1);
            fma2(acc[6][2], z67.x, e2); fma2(acc[6][3], z67.x, e3);
            fma2(acc[7][0], z67.y, e0); fma2(acc[7][1], z67.y, e1);
            fma2(acc[7][2], z67.y, e2); fma2(acc[7][3], z67.y, e3);
        }

        // d = fl( fl(a+b) - 2c ), strict-< argmin (first-index), ascending codes
#pragma unroll
        for (int m = 0; m < 4; ++m) {
            const int cbase = c0 + m * 64 + 2 * lane;
#pragma unroll
            for (int r = 0; r < 8; ++r) {
                float lo, hi;
                unpack2(acc[r][m], lo, hi);
                float d0 = fmaf(-2.f, lo, __fadd_rn(a8[r], bn[m * 2 + 0]));
                if (d0 < best[r]) { best[r] = d0; bidx[r] = cbase; }
                float d1 = fmaf(-2.f, hi, __fadd_rn(a8[r], bn[m * 2 + 1]));
                if (d1 < best[r]) { best[r] = d1; bidx[r] = cbase + 1; }
            }
        }

        __syncthreads();     // all threads done reading e buffer (t&1)
        int tn = t + 2;
        if (tn < NT) {
#pragma unroll
            for (int j = 0; j < 16; ++j) {
                int idx = tid + j * 256;
                int kk = idx >> 6;
                int c4 = idx & 63;
                cp_async16(smem_e0 + (unsigned)((tn & 1) * SM_E_BUF + (kk * CT + c4 * 4) * 4),
                           g_embT + (size_t)kk * N_CODES + tn * CT + c4 * 4);
            }
            cp_commit();
        }
    }

    // Cross-lane argmin (32 lanes), first-index tie-break
#pragma unroll
    for (int off = 1; off < 32; off <<= 1) {
#pragma unroll
        for (int r = 0; r < 8; ++r) {
            float ov = __shfl_xor_sync(0xffffffffu, best[r], off);
            int   oi = __shfl_xor_sync(0xffffffffu, bidx[r], off);
            if (ov < best[r] || (ov == best[r] && oi < bidx[r])) {
                best[r] = ov; bidx[r] = oi;
            }
        }
    }
    if (lane == 0) {
#pragma unroll
        for (int r = 0; r < 8; ++r) idx_s[w * 8 + r] = bidx[r];
    }
    __syncthreads();

    if (tid < M_TILE) g_idx_buf[row0 + tid] = idx_s[tid];

    // z_q write + loss partial (identical indexing/arithmetic to round-2)
    float lsum = 0.f;
    for (int i = tid; i < M_TILE * EMB_DIM; i += 256) {
        int r = i >> 6, k = i & 63;
        float e = emb[(size_t)idx_s[r] * EMB_DIM + k];
        float diff = e - zd[k * ZD_STRIDE + r].x;
        lsum = fmaf(diff, diff, lsum);
        zq_out[(row0 + r) * EMB_DIM + k] = e;
    }

    red_s[tid] = lsum;
    __syncthreads();
#pragma unroll
    for (int s = 128; s > 0; s >>= 1) {
        if (tid < s) red_s[tid] += red_s[tid + s];
        __syncthreads();
    }
    if (tid == 0) g_partials[blockIdx.x] = red_s[0];
}

// ---------------------------------------------------------------------------
// Kernel 3: deterministic final loss reduction
// ---------------------------------------------------------------------------
__global__ void vq_loss_kernel(float* __restrict__ out, int loss_off) {
    __shared__ float red_s[256];
    const int tid = threadIdx.x;
    float s = 0.f;
#pragma unroll
    for (int j = 0; j < N_BLOCKS / 256; ++j)
        s += g_partials[tid + j * 256];
    red_s[tid] = s;
    __syncthreads();
#pragma unroll
    for (int st = 128; st > 0; st >>= 1) {
        if (tid < st) red_s[tid] += red_s[tid + st];
        __syncthreads();
    }
    if (tid == 0 && loss_off >= 0)
        out[loss_off] = (1.0f + BETA) * (red_s[0] / (float)NZ_ELEMS);
}

// ---------------------------------------------------------------------------
// Kernel 4: indices -> float into output tail
// ---------------------------------------------------------------------------
__global__ void vq_idx_kernel(float* __restrict__ out_idx) {
    int i = blockIdx.x * blockDim.x + threadIdx.x;
    if (i < N_ROWS) out_idx[i] = (float)g_idx_buf[i];
}

// ---------------------------------------------------------------------------
extern "C" void kernel_launch(void* const* d_in, const int* in_sizes, int n_in,
                              void* d_out, int out_size) {
    const float* z   = (const float*)d_in[0];
    const float* emb = (const float*)d_in[1];
    float* out = (float*)d_out;

    static int smem_set = 0; // attribute set is idempotent; harmless every call
    cudaFuncSetAttribute(vq_main_kernel,
                         cudaFuncAttributeMaxDynamicSharedMemorySize, SM_TOTAL);
    (void)smem_set;

    vq_transpose_kernel<<<(EMB_DIM * N_CODES + 255) / 256, 256>>>(emb);
    vq_enorm_kernel<<<(N_CODES + 255) / 256, 256>>>(emb);
    vq_main_kernel<<<N_BLOCKS, 256, SM_TOTAL>>>(z, emb, out);

    long loss_off = -1, idx_off = -1;
    if (out_size >= NZ_ELEMS + 1 + N_ROWS) {        // z_q, loss, idx
        loss_off = NZ_ELEMS; idx_off = NZ_ELEMS + 1;
    } else if (out_size == NZ_ELEMS + N_ROWS) {     // z_q, idx
        idx_off = NZ_ELEMS;
    } else if (out_size == NZ_ELEMS + 1) {          // z_q, loss
        loss_off = NZ_ELEMS;
    }

    vq_loss_kernel<<<1, 256>>>(out, (int)loss_off);
    if (idx_off >= 0)
        vq_idx_kernel<<<(N_ROWS + 255) / 256, 256>>>(out + idx_off);
}